// round 2
// baseline (speedup 1.0000x reference)
#include <cuda_runtime.h>
#include <cuda_bf16.h>

// out shape (1, 8, 4096, 4096) fp32.
// c in 0..3:  out[c][i][j] = table[seq[i]*4 + c]      (row splat)
// c in 4..7:  out[c][i][j] = table[seq[j]*4 + (c-4)]  (same pattern every row)
//
// Pure store-bandwidth kernel: one block per (c,i) row, 256 threads,
// 4x float4 streaming stores per thread (4096 floats = 16KB per row).

#define L 4096
#define NB 4

__global__ __launch_bounds__(256, 8)
void seq_embed_kernel(const int* __restrict__ seq,
                      const float* __restrict__ table,
                      float* __restrict__ out)
{
    const int i = blockIdx.x;   // 0..4095
    const int c = blockIdx.y;   // 0..7

    __shared__ float tbl[NB * NB];
    if (threadIdx.x < NB * NB) tbl[threadIdx.x] = table[threadIdx.x];
    __syncthreads();

    float4* row4 = reinterpret_cast<float4*>(
        out + (((size_t)c * L) + (size_t)i) * (size_t)L);

    if (c < NB) {
        // value constant across the row
        const float v = tbl[seq[i] * NB + c];
        const float4 f4 = make_float4(v, v, v, v);
#pragma unroll
        for (int k = 0; k < 4; ++k) {
            const int j4 = threadIdx.x + 256 * k;   // float4 index, coalesced
            __stcs(row4 + j4, f4);
        }
    } else {
        const int cc = c - NB;
        const int4* seq4 = reinterpret_cast<const int4*>(seq);
#pragma unroll
        for (int k = 0; k < 4; ++k) {
            const int j4 = threadIdx.x + 256 * k;
            const int4 s = __ldg(seq4 + j4);        // 16KB total, L2-resident
            const float4 f4 = make_float4(tbl[s.x * NB + cc],
                                          tbl[s.y * NB + cc],
                                          tbl[s.z * NB + cc],
                                          tbl[s.w * NB + cc]);
            __stcs(row4 + j4, f4);
        }
    }
}

extern "C" void kernel_launch(void* const* d_in, const int* in_sizes, int n_in,
                              void* d_out, int out_size)
{
    const int*   seq   = (const int*)d_in[0];    // seq_ids (int32; see dtype note)
    const float* table = (const float*)d_in[1];  // base_table (4x4 identity-like)
    float*       out   = (float*)d_out;          // (1, 8, 4096, 4096) fp32

    dim3 grid(L, 2 * NB);
    seq_embed_kernel<<<grid, 256>>>(seq, table, out);
}